// round 1
// baseline (speedup 1.0000x reference)
#include <cuda_runtime.h>
#include <stdint.h>

#define NC   151          // classes incl. background
#define CM1  150
#define DIM  2048
#define NB   128          // images
#define NP   512          // pairs per image
#define CAP  16           // max absent classes handled in smem (fallback to global beyond)

// ---------------- device scratch (allowed: __device__ globals) ----------------
__device__ float g_sym[NC * NC];          // (score + score^T)/2
__device__ float g_WT[600 * DIM];         // lin_w transposed: WT[col][d] = lin_w[d][col]
__device__ float g_T0[NC * DIM];          // T0[c][d] = sum_e sym[c,e]*W[:,e-1] + W[:,300+c-1] + 0.5*b
__device__ float g_T1[NC * DIM];          // T1[c][d] = sum_e sym[c,e]*W[:,150+e-1] + W[:,450+c-1] + 0.5*b
__device__ int   g_abs_cnt[NB];
__device__ int   g_abs_list[NB * CM1];

// ---------------- small float4 helpers ----------------
__device__ __forceinline__ float4 f4add(float4 a, float4 b) {
    return make_float4(a.x + b.x, a.y + b.y, a.z + b.z, a.w + b.w);
}
__device__ __forceinline__ float4 f4fma(float s, float4 a, float4 acc) {
    acc.x = fmaf(s, a.x, acc.x); acc.y = fmaf(s, a.y, acc.y);
    acc.z = fmaf(s, a.z, acc.z); acc.w = fmaf(s, a.w, acc.w);
    return acc;
}
__device__ __forceinline__ float4 f4fms(float s, float4 a, float4 acc) { // acc -= s*a
    acc.x = fmaf(-s, a.x, acc.x); acc.y = fmaf(-s, a.y, acc.y);
    acc.z = fmaf(-s, a.z, acc.z); acc.w = fmaf(-s, a.w, acc.w);
    return acc;
}

// pairs may arrive as int64 (JAX x64) or int32 (JAX default). Values are >= 1
// always, so: if the second 32-bit word is 0 it must be the high half of an
// int64 -> is64 = 1. Element i then lives at p32[i << is64] (little-endian).
__device__ __forceinline__ int pairs_is64(const int* p32) { return (p32[1] == 0) ? 1 : 0; }

// ---------------- kernel 1: sym table + per-image absent-class lists ----------------
__global__ void k_prep(const void* __restrict__ pairs_v, const float* __restrict__ score) {
    const int* p32 = (const int*)pairs_v;
    int tid = threadIdx.x;
    if (blockIdx.x == 0) {
        for (int idx = tid; idx < NC * NC; idx += blockDim.x) {
            int c = idx / NC, e = idx % NC;
            g_sym[idx] = 0.5f * (score[c * NC + e] + score[e * NC + c]);
        }
    } else {
        int b = blockIdx.x - 1;
        int is64 = pairs_is64(p32);
        __shared__ int flags[NC];
        for (int i = tid; i < NC; i += blockDim.x) flags[i] = 0;
        __syncthreads();
        for (int i = tid; i < 2 * NP; i += blockDim.x) {
            size_t ei = (size_t)b * 2 * NP + i;
            int v = p32[ei << is64];
            flags[v] = 1;
        }
        __syncthreads();
        if (tid == 0) {  // single-thread scan -> deterministic ordered list
            int cnt = 0;
            for (int e = 1; e < NC; ++e)
                if (!flags[e]) g_abs_list[b * CM1 + cnt++] = e;
            g_abs_cnt[b] = cnt;
        }
    }
}

// ---------------- kernel 2: transpose lin_w [2048,600] -> WT [600,2048] ----------------
__global__ void k_trans(const float* __restrict__ w) {
    __shared__ float t[32][33];
    int j0 = blockIdx.x * 32, d0 = blockIdx.y * 32;
    int tx = threadIdx.x, ty = threadIdx.y;   // block (32, 8)
    for (int r = ty; r < 32; r += 8) {
        int d = d0 + r, j = j0 + tx;
        t[r][tx] = (j < 600) ? w[(size_t)d * 600 + j] : 0.f;
    }
    __syncthreads();
    for (int r = ty; r < 32; r += 8) {
        int j = j0 + r;
        if (j < 600) g_WT[(size_t)j * DIM + d0 + tx] = t[tx][r];
    }
}

// ---------------- kernel 3: dense class tables T0/T1 ----------------
// grid (19, 2), block 512. Each block: 8 classes x full 2048 dim for one half.
__global__ void k_tables(const float* __restrict__ lb) {
    int which = blockIdx.y;
    int cBase = blockIdx.x * 8;
    __shared__ float ssym[8][NC + 1];
    int tid = threadIdx.x;
    for (int idx = tid; idx < 8 * NC; idx += 512) {
        int ci = idx / NC, e = idx % NC;
        int c = cBase + ci;
        ssym[ci][e] = (c < NC) ? g_sym[c * NC + e] : 0.f;
    }
    __syncthreads();
    const float4* WT4 = (const float4*)g_WT;
    int d4 = tid;                 // float4 column 0..511
    float4 acc[8];
#pragma unroll
    for (int ci = 0; ci < 8; ++ci) acc[ci] = make_float4(0.f, 0.f, 0.f, 0.f);
    int base = which * CM1;       // WT row block: 0 for e0-weights, 150 for e1-weights
    for (int e = 1; e < NC; ++e) {
        float4 wv = WT4[(size_t)(base + e - 1) * (DIM / 4) + d4];
#pragma unroll
        for (int ci = 0; ci < 8; ++ci) acc[ci] = f4fma(ssym[ci][e], wv, acc[ci]);
    }
    float4 hb = ((const float4*)lb)[d4];
    hb.x *= 0.5f; hb.y *= 0.5f; hb.z *= 0.5f; hb.w *= 0.5f;
    float* Tdst = which ? g_T1 : g_T0;
#pragma unroll
    for (int ci = 0; ci < 8; ++ci) {
        int c = cBase + ci;
        if (c >= NC) continue;
        float4 v = f4add(acc[ci], hb);
        if (c >= 1) {
            // one-hot position column: 300 + which*150 + (c-1)
            float4 pv = WT4[(size_t)(300 + which * CM1 + c - 1) * (DIM / 4) + d4];
            v = f4add(v, pv);
        }
        ((float4*)Tdst)[(size_t)c * (DIM / 4) + d4] = v;
    }
}

// ---------------- kernel 4: main gather/add ----------------
// grid (128 images, 16 chunks of 128 cols), block 256, ~175KB dynamic smem.
__global__ void __launch_bounds__(256) k_main(const void* __restrict__ pairs_v,
                                              float* __restrict__ out) {
    extern __shared__ float4 smem[];
    float4* s0 = smem;                       // NC*32 float4
    float4* s1 = s0 + NC * 32;               // NC*32 float4
    float4* wa = s1 + NC * 32;               // CAP*32 float4
    float4* wb = wa + CAP * 32;              // CAP*32 float4
    int* sp = (int*)(wb + CAP * 32);         // 2*NP ints
    int* slist = sp + 2 * NP;                // CAP ints
    __shared__ int scnt;

    const int* p32 = (const int*)pairs_v;
    int is64 = pairs_is64(p32);
    int b = blockIdx.x, chunk = blockIdx.y;
    int tid = threadIdx.x;
    int cb = chunk * 32;                     // float4 offset within a 2048-row

    if (tid == 0) scnt = g_abs_cnt[b];
    if (tid < CAP) slist[tid] = g_abs_list[b * CM1 + tid];

    const float4* T04 = (const float4*)g_T0;
    const float4* T14 = (const float4*)g_T1;
    for (int idx = tid; idx < NC * 32; idx += 256) {
        int c = idx >> 5, j = idx & 31;
        s0[idx] = T04[(size_t)c * (DIM / 4) + cb + j];
        s1[idx] = T14[(size_t)c * (DIM / 4) + cb + j];
    }
    for (int i = tid; i < 2 * NP; i += 256) {
        size_t ei = (size_t)b * 2 * NP + i;
        sp[i] = p32[ei << is64];
    }
    __syncthreads();

    int cnt = scnt;
    int kc = cnt < CAP ? cnt : CAP;
    const float4* WT4 = (const float4*)g_WT;
    for (int idx = tid; idx < kc * 32; idx += 256) {
        int k = idx >> 5, j = idx & 31;
        int e = slist[k];
        wa[idx] = WT4[(size_t)(e - 1) * (DIM / 4) + cb + j];
        wb[idx] = WT4[(size_t)(CM1 + e - 1) * (DIM / 4) + cb + j];
    }
    __syncthreads();

    int j = tid & 31, sub = tid >> 5;
    float4* out4 = (float4*)out;
    for (int it = 0; it < NP / 8; ++it) {
        int p = it * 8 + sub;
        int p0 = sp[2 * p], p1 = sp[2 * p + 1];
        float4 v = f4add(s0[p0 * 32 + j], s1[p1 * 32 + j]);
        for (int k = 0; k < kc; ++k) {
            int e = slist[k];
            float c0 = g_sym[p0 * NC + e];
            float c1 = g_sym[p1 * NC + e];
            v = f4fms(c0, wa[k * 32 + j], v);
            v = f4fms(c1, wb[k * 32 + j], v);
        }
        if (cnt > CAP) {   // essentially-never fallback, kept for exactness
            for (int k = CAP; k < cnt; ++k) {
                int e = g_abs_list[b * CM1 + k];
                float c0 = g_sym[p0 * NC + e];
                float c1 = g_sym[p1 * NC + e];
                float4 a = WT4[(size_t)(e - 1) * (DIM / 4) + cb + j];
                float4 bb = WT4[(size_t)(CM1 + e - 1) * (DIM / 4) + cb + j];
                v = f4fms(c0, a, v);
                v = f4fms(c1, bb, v);
            }
        }
        out4[(size_t)(b * NP + p) * (DIM / 4) + cb + j] = v;
    }
}

// ---------------- launch ----------------
static const size_t SMEM_MAIN =
    (size_t)(2 * NC * 32 + 2 * CAP * 32) * sizeof(float4) + (2 * NP + CAP) * sizeof(int);

extern "C" void kernel_launch(void* const* d_in, const int* in_sizes, int n_in,
                              void* d_out, int out_size) {
    const void*  pairs = d_in[0];
    const float* score = (const float*)d_in[1];
    const float* lw    = (const float*)d_in[2];
    const float* lb    = (const float*)d_in[3];
    float* out = (float*)d_out;
    (void)in_sizes; (void)n_in; (void)out_size;

    cudaFuncSetAttribute(k_main, cudaFuncAttributeMaxDynamicSharedMemorySize, (int)SMEM_MAIN);

    k_prep  <<<NB + 1, 256>>>(pairs, score);
    k_trans <<<dim3(19, 64), dim3(32, 8)>>>(lw);
    k_tables<<<dim3(19, 2), 512>>>(lb);
    k_main  <<<dim3(NB, 16), 256, SMEM_MAIN>>>(pairs, out);
}

// round 3
// speedup vs baseline: 1.4034x; 1.4034x over previous
#include <cuda_runtime.h>
#include <stdint.h>

#define NC   151          // classes incl. background
#define CM1  150
#define DIM  2048
#define NB   128          // images
#define NP   512          // pairs per image
#define CAP  16           // max absent classes handled in smem (fallback beyond)
#define NCHUNK 16         // 2048 / 128 cols
#define TPB  1024

// ---------------- device scratch ----------------
__device__ float g_sym[NC * NC];
__device__ float g_WT[600 * DIM];         // lin_w transposed
__device__ float g_T0[NC * DIM];
__device__ float g_T1[NC * DIM];
__device__ int   g_abs_cnt[NB];
__device__ int   g_abs_list[NB * CM1];

// ---------------- float4 helpers ----------------
__device__ __forceinline__ float4 f4add(float4 a, float4 b) {
    return make_float4(a.x + b.x, a.y + b.y, a.z + b.z, a.w + b.w);
}
__device__ __forceinline__ float4 f4fma(float s, float4 a, float4 acc) {
    acc.x = fmaf(s, a.x, acc.x); acc.y = fmaf(s, a.y, acc.y);
    acc.z = fmaf(s, a.z, acc.z); acc.w = fmaf(s, a.w, acc.w);
    return acc;
}
__device__ __forceinline__ float4 f4fms(float s, float4 a, float4 acc) {
    acc.x = fmaf(-s, a.x, acc.x); acc.y = fmaf(-s, a.y, acc.y);
    acc.z = fmaf(-s, a.z, acc.z); acc.w = fmaf(-s, a.w, acc.w);
    return acc;
}

// int64-vs-int32 detection (all pair values >= 1, little-endian)
__device__ __forceinline__ int pairs_is64(const int* p32) { return (p32[1] == 0) ? 1 : 0; }

// ---------------- kernel 1: sym table + per-image absent-class lists ----------------
__global__ void k_prep(const void* __restrict__ pairs_v, const float* __restrict__ score) {
    const int* p32 = (const int*)pairs_v;
    int tid = threadIdx.x;
    if (blockIdx.x == 0) {
        for (int idx = tid; idx < NC * NC; idx += blockDim.x) {
            int c = idx / NC, e = idx % NC;
            g_sym[idx] = 0.5f * (score[c * NC + e] + score[e * NC + c]);
        }
    } else {
        int b = blockIdx.x - 1;
        int is64 = pairs_is64(p32);
        __shared__ int flags[NC];
        for (int i = tid; i < NC; i += blockDim.x) flags[i] = 0;
        __syncthreads();
        for (int i = tid; i < 2 * NP; i += blockDim.x) {
            size_t ei = (size_t)b * 2 * NP + i;
            flags[p32[ei << is64]] = 1;
        }
        __syncthreads();
        if (tid == 0) {
            int cnt = 0;
            for (int e = 1; e < NC; ++e)
                if (!flags[e]) g_abs_list[b * CM1 + cnt++] = e;
            g_abs_cnt[b] = cnt;
        }
    }
}

// ---------------- kernel 2: transpose lin_w [2048,600] -> WT [600,2048] ----------------
__global__ void k_trans(const float* __restrict__ w) {
    __shared__ float t[32][33];
    int j0 = blockIdx.x * 32, d0 = blockIdx.y * 32;
    int tx = threadIdx.x, ty = threadIdx.y;   // block (32, 8)
    for (int r = ty; r < 32; r += 8) {
        int d = d0 + r, j = j0 + tx;
        t[r][tx] = (j < 600) ? w[(size_t)d * 600 + j] : 0.f;
    }
    __syncthreads();
    for (int r = ty; r < 32; r += 8) {
        int j = j0 + r;
        if (j < 600) g_WT[(size_t)j * DIM + d0 + tx] = t[tx][r];
    }
}

// ---------------- kernel 3: dense class tables T0/T1 ----------------
// grid (19, 2, 4), block 128. 8 classes x 128 float4-cols per block.
__global__ void k_tables(const float* __restrict__ lb) {
    int which = blockIdx.y;
    int cBase = blockIdx.x * 8;
    __shared__ float ssym[8][NC + 1];
    int tid = threadIdx.x;
    for (int idx = tid; idx < 8 * NC; idx += 128) {
        int ci = idx / NC, e = idx % NC;
        int c = cBase + ci;
        ssym[ci][e] = (c < NC) ? g_sym[c * NC + e] : 0.f;
    }
    __syncthreads();
    const float4* WT4 = (const float4*)g_WT;
    int d4 = blockIdx.z * 128 + tid;          // float4 column 0..511
    float4 acc[8];
#pragma unroll
    for (int ci = 0; ci < 8; ++ci) acc[ci] = make_float4(0.f, 0.f, 0.f, 0.f);
    int base = which * CM1;
    for (int e = 1; e < NC; ++e) {
        float4 wv = WT4[(size_t)(base + e - 1) * (DIM / 4) + d4];
#pragma unroll
        for (int ci = 0; ci < 8; ++ci) acc[ci] = f4fma(ssym[ci][e], wv, acc[ci]);
    }
    float4 hb = ((const float4*)lb)[d4];
    hb.x *= 0.5f; hb.y *= 0.5f; hb.z *= 0.5f; hb.w *= 0.5f;
    float* Tdst = which ? g_T1 : g_T0;
#pragma unroll
    for (int ci = 0; ci < 8; ++ci) {
        int c = cBase + ci;
        if (c >= NC) continue;
        float4 v = f4add(acc[ci], hb);
        if (c >= 1) {
            float4 pv = WT4[(size_t)(300 + which * CM1 + c - 1) * (DIM / 4) + d4];
            v = f4add(v, pv);
        }
        ((float4*)Tdst)[(size_t)c * (DIM / 4) + d4] = v;
    }
}

// ---------------- kernel 4: persistent gather/add ----------------
// grid 148 persistent blocks, 1024 threads, ~175KB dynamic smem.
// Work items ordered chunk-major so a block reloads tables at most ~2x.
__global__ void __launch_bounds__(TPB) k_main(const void* __restrict__ pairs_v,
                                              float* __restrict__ out) {
    extern __shared__ float4 smem[];
    float4* s0 = smem;                       // NC*32
    float4* s1 = s0 + NC * 32;               // NC*32
    float4* wa = s1 + NC * 32;               // CAP*32
    float4* wb = wa + CAP * 32;              // CAP*32
    int* sp = (int*)(wb + CAP * 32);         // 2*NP = 1024
    int* slist = sp + 2 * NP;                // CAP
    __shared__ int scnt;

    const int* p32 = (const int*)pairs_v;
    int is64 = pairs_is64(p32);
    int tid = threadIdx.x;
    const float4* T04 = (const float4*)g_T0;
    const float4* T14 = (const float4*)g_T1;
    const float4* WT4 = (const float4*)g_WT;
    float4* out4 = (float4*)out;

    const int nitems = NCHUNK * NB;          // 2048
    int start = (int)(((long)nitems * blockIdx.x) / gridDim.x);
    int end   = (int)(((long)nitems * (blockIdx.x + 1)) / gridDim.x);
    int cur_chunk = -1;

    for (int item = start; item < end; ++item) {
        int chunk = item >> 7;               // item / NB
        int b = item & (NB - 1);
        int cb = chunk * 32;

        __syncthreads();                     // protect s0/s1/sp/wa reuse from prior item
        if (chunk != cur_chunk) {
            for (int idx = tid; idx < NC * 32; idx += TPB) {
                int c = idx >> 5, j = idx & 31;
                s0[idx] = T04[(size_t)c * (DIM / 4) + cb + j];
                s1[idx] = T14[(size_t)c * (DIM / 4) + cb + j];
            }
            cur_chunk = chunk;
        }
        // pairs (exactly 1024 ints with 1024 threads) + absent list
        sp[tid] = p32[((size_t)b * 2 * NP + tid) << is64];
        if (tid < CAP) slist[tid] = g_abs_list[b * CM1 + tid];
        if (tid == 0) scnt = g_abs_cnt[b];
        __syncthreads();

        int cnt = scnt;
        int kc = cnt < CAP ? cnt : CAP;
        for (int idx = tid; idx < kc * 32; idx += TPB) {
            int k = idx >> 5, j = idx & 31;
            int e = slist[k];
            wa[idx] = WT4[(size_t)(e - 1) * (DIM / 4) + cb + j];
            wb[idx] = WT4[(size_t)(CM1 + e - 1) * (DIM / 4) + cb + j];
        }
        if (kc) __syncthreads();

        int j = tid & 31, sub = tid >> 5;    // sub in 0..31
#pragma unroll 4
        for (int it = 0; it < NP / 32; ++it) {
            int p = it * 32 + sub;
            int p0 = sp[2 * p], p1 = sp[2 * p + 1];
            float4 v = f4add(s0[p0 * 32 + j], s1[p1 * 32 + j]);
            for (int k = 0; k < kc; ++k) {
                int e = slist[k];
                v = f4fms(g_sym[p0 * NC + e], wa[k * 32 + j], v);
                v = f4fms(g_sym[p1 * NC + e], wb[k * 32 + j], v);
            }
            if (cnt > CAP) {                 // essentially-never exact fallback
                for (int k = CAP; k < cnt; ++k) {
                    int e = g_abs_list[b * CM1 + k];
                    float4 a  = WT4[(size_t)(e - 1) * (DIM / 4) + cb + j];
                    float4 bb = WT4[(size_t)(CM1 + e - 1) * (DIM / 4) + cb + j];
                    v = f4fms(g_sym[p0 * NC + e], a, v);
                    v = f4fms(g_sym[p1 * NC + e], bb, v);
                }
            }
            out4[(size_t)(b * NP + p) * (DIM / 4) + cb + j] = v;
        }
    }
}

// ---------------- launch ----------------
static const size_t SMEM_MAIN =
    (size_t)(2 * NC * 32 + 2 * CAP * 32) * sizeof(float4) + (2 * NP + CAP) * sizeof(int);

extern "C" void kernel_launch(void* const* d_in, const int* in_sizes, int n_in,
                              void* d_out, int out_size) {
    const void*  pairs = d_in[0];
    const float* score = (const float*)d_in[1];
    const float* lw    = (const float*)d_in[2];
    const float* lb    = (const float*)d_in[3];
    float* out = (float*)d_out;
    (void)in_sizes; (void)n_in; (void)out_size;

    cudaFuncSetAttribute(k_main, cudaFuncAttributeMaxDynamicSharedMemorySize, (int)SMEM_MAIN);

    k_prep  <<<NB + 1, 256>>>(pairs, score);
    k_trans <<<dim3(19, 64), dim3(32, 8)>>>(lw);
    k_tables<<<dim3(19, 2, 4), 128>>>(lb);
    k_main  <<<148, TPB, SMEM_MAIN>>>(pairs, out);
}

// round 4
// speedup vs baseline: 1.5372x; 1.0954x over previous
#include <cuda_runtime.h>
#include <stdint.h>

#define NC   151          // classes incl. background
#define CM1  150
#define DIM  2048
#define NB   128          // images
#define NP   512          // pairs per image
#define CAP  16           // max absent classes handled in smem (fallback beyond)
#define CHW  16           // float4 per chunk row (64 floats)
#define NCHUNK (DIM / 4 / CHW)   // 32
#define TPB  1024

// ---------------- device scratch ----------------
__device__ float g_sym[NC * NC];
__device__ float g_WT[600 * DIM];         // lin_w transposed
__device__ float g_T0[NC * DIM];
__device__ float g_T1[NC * DIM];
__device__ int   g_abs_cnt[NB];
__device__ int   g_abs_list[NB * CM1];

// ---------------- float4 helpers ----------------
__device__ __forceinline__ float4 f4add(float4 a, float4 b) {
    return make_float4(a.x + b.x, a.y + b.y, a.z + b.z, a.w + b.w);
}
__device__ __forceinline__ float4 f4fma(float s, float4 a, float4 acc) {
    acc.x = fmaf(s, a.x, acc.x); acc.y = fmaf(s, a.y, acc.y);
    acc.z = fmaf(s, a.z, acc.z); acc.w = fmaf(s, a.w, acc.w);
    return acc;
}
__device__ __forceinline__ float4 f4fms(float s, float4 a, float4 acc) {
    acc.x = fmaf(-s, a.x, acc.x); acc.y = fmaf(-s, a.y, acc.y);
    acc.z = fmaf(-s, a.z, acc.z); acc.w = fmaf(-s, a.w, acc.w);
    return acc;
}

// int64-vs-int32 detection (all pair values >= 1, little-endian)
__device__ __forceinline__ int pairs_is64(const int* p32) { return (p32[1] == 0) ? 1 : 0; }

// ---------------- kernel 1: sym table + per-image absent-class lists ----------------
__global__ void k_prep(const void* __restrict__ pairs_v, const float* __restrict__ score) {
    const int* p32 = (const int*)pairs_v;
    int tid = threadIdx.x;
    if (blockIdx.x == 0) {
        for (int idx = tid; idx < NC * NC; idx += blockDim.x) {
            int c = idx / NC, e = idx % NC;
            g_sym[idx] = 0.5f * (score[c * NC + e] + score[e * NC + c]);
        }
    } else {
        int b = blockIdx.x - 1;
        int is64 = pairs_is64(p32);
        __shared__ int flags[NC];
        for (int i = tid; i < NC; i += blockDim.x) flags[i] = 0;
        __syncthreads();
        for (int i = tid; i < 2 * NP; i += blockDim.x) {
            size_t ei = (size_t)b * 2 * NP + i;
            flags[p32[ei << is64]] = 1;
        }
        __syncthreads();
        if (tid == 0) {
            int cnt = 0;
            for (int e = 1; e < NC; ++e)
                if (!flags[e]) g_abs_list[b * CM1 + cnt++] = e;
            g_abs_cnt[b] = cnt;
        }
    }
}

// ---------------- kernel 2: transpose lin_w [2048,600] -> WT [600,2048] ----------------
__global__ void k_trans(const float* __restrict__ w) {
    __shared__ float t[32][33];
    int j0 = blockIdx.x * 32, d0 = blockIdx.y * 32;
    int tx = threadIdx.x, ty = threadIdx.y;   // block (32, 8)
    for (int r = ty; r < 32; r += 8) {
        int d = d0 + r, j = j0 + tx;
        t[r][tx] = (j < 600) ? w[(size_t)d * 600 + j] : 0.f;
    }
    __syncthreads();
    for (int r = ty; r < 32; r += 8) {
        int j = j0 + r;
        if (j < 600) g_WT[(size_t)j * DIM + d0 + tx] = t[tx][r];
    }
}

// ---------------- kernel 3: dense class tables T0/T1 ----------------
// grid (19, 2, 8), block 64. 8 classes x 64 float4-cols per block.
__global__ void k_tables(const float* __restrict__ lb) {
    int which = blockIdx.y;
    int cBase = blockIdx.x * 8;
    __shared__ float ssym[8][NC + 1];
    int tid = threadIdx.x;
    for (int idx = tid; idx < 8 * NC; idx += 64) {
        int ci = idx / NC, e = idx % NC;
        int c = cBase + ci;
        ssym[ci][e] = (c < NC) ? g_sym[c * NC + e] : 0.f;
    }
    __syncthreads();
    const float4* WT4 = (const float4*)g_WT;
    int d4 = blockIdx.z * 64 + tid;
    float4 acc[8];
#pragma unroll
    for (int ci = 0; ci < 8; ++ci) acc[ci] = make_float4(0.f, 0.f, 0.f, 0.f);
    int base = which * CM1;
#pragma unroll 2
    for (int e = 1; e < NC; ++e) {
        float4 wv = WT4[(size_t)(base + e - 1) * (DIM / 4) + d4];
#pragma unroll
        for (int ci = 0; ci < 8; ++ci) acc[ci] = f4fma(ssym[ci][e], wv, acc[ci]);
    }
    float4 hb = ((const float4*)lb)[d4];
    hb.x *= 0.5f; hb.y *= 0.5f; hb.z *= 0.5f; hb.w *= 0.5f;
    float* Tdst = which ? g_T1 : g_T0;
#pragma unroll
    for (int ci = 0; ci < 8; ++ci) {
        int c = cBase + ci;
        if (c >= NC) continue;
        float4 v = f4add(acc[ci], hb);
        if (c >= 1) {
            float4 pv = WT4[(size_t)(300 + which * CM1 + c - 1) * (DIM / 4) + d4];
            v = f4add(v, pv);
        }
        ((float4*)Tdst)[(size_t)c * (DIM / 4) + d4] = v;
    }
}

// ---------------- rare exact fallback (keeps main loop register-lean) ----------------
__device__ __noinline__ float4 fallback_corr(float4 v, int b, int p0, int p1,
                                             int cb, int j, int cnt) {
    const float4* WT4 = (const float4*)g_WT;
    for (int k = CAP; k < cnt; ++k) {
        int e = g_abs_list[b * CM1 + k];
        float4 a  = WT4[(size_t)(e - 1) * (DIM / 4) + cb + j];
        float4 bb = WT4[(size_t)(CM1 + e - 1) * (DIM / 4) + cb + j];
        v = f4fms(g_sym[p0 * NC + e], a, v);
        v = f4fms(g_sym[p1 * NC + e], bb, v);
    }
    return v;
}

// ---------------- kernel 4: persistent gather/add ----------------
// grid 296 (2 blocks/SM), 1024 threads, ~89.7KB dynamic smem each.
__global__ void __launch_bounds__(TPB, 2) k_main(const void* __restrict__ pairs_v,
                                                 float* __restrict__ out) {
    extern __shared__ float4 smem[];
    float4* s0 = smem;                       // NC*CHW
    float4* s1 = s0 + NC * CHW;              // NC*CHW
    float4* wa = s1 + NC * CHW;              // CAP*CHW
    float4* wb = wa + CAP * CHW;             // CAP*CHW
    int* sp = (int*)(wb + CAP * CHW);        // 2*NP = 1024
    int* slist = sp + 2 * NP;                // CAP
    __shared__ int scnt;

    const int* p32 = (const int*)pairs_v;
    int is64 = pairs_is64(p32);
    int tid = threadIdx.x;
    const float4* T04 = (const float4*)g_T0;
    const float4* T14 = (const float4*)g_T1;
    const float4* WT4 = (const float4*)g_WT;
    float4* out4 = (float4*)out;

    const int nitems = NCHUNK * NB;          // 4096
    int start = (int)(((long)nitems * blockIdx.x) / gridDim.x);
    int end   = (int)(((long)nitems * (blockIdx.x + 1)) / gridDim.x);
    int cur_chunk = -1;

    for (int item = start; item < end; ++item) {
        int chunk = item >> 7;               // item / NB
        int b = item & (NB - 1);
        int cb = chunk * CHW;

        __syncthreads();                     // protect smem reuse from prior item
        if (chunk != cur_chunk) {
            for (int idx = tid; idx < NC * CHW; idx += TPB) {
                int c = idx / CHW, j = idx % CHW;
                s0[idx] = T04[(size_t)c * (DIM / 4) + cb + j];
                s1[idx] = T14[(size_t)c * (DIM / 4) + cb + j];
            }
            cur_chunk = chunk;
        }
        sp[tid] = p32[((size_t)b * 2 * NP + tid) << is64];
        if (tid < CAP) slist[tid] = g_abs_list[b * CM1 + tid];
        if (tid == 0) scnt = g_abs_cnt[b];
        __syncthreads();

        int cnt = scnt;
        int kc = cnt < CAP ? cnt : CAP;
        for (int idx = tid; idx < kc * CHW; idx += TPB) {
            int k = idx / CHW, j = idx % CHW;
            int e = slist[k];
            wa[idx] = WT4[(size_t)(e - 1) * (DIM / 4) + cb + j];
            wb[idx] = WT4[(size_t)(CM1 + e - 1) * (DIM / 4) + cb + j];
        }
        if (kc) __syncthreads();

        int j = tid & (CHW - 1), sub = tid >> 4;   // sub in 0..63
#pragma unroll 4
        for (int it = 0; it < NP / 64; ++it) {
            int p = it * 64 + sub;
            int p0 = sp[2 * p], p1 = sp[2 * p + 1];
            float4 v = f4add(s0[p0 * CHW + j], s1[p1 * CHW + j]);
            for (int k = 0; k < kc; ++k) {
                int e = slist[k];
                v = f4fms(g_sym[p0 * NC + e], wa[k * CHW + j], v);
                v = f4fms(g_sym[p1 * NC + e], wb[k * CHW + j], v);
            }
            if (cnt > CAP) v = fallback_corr(v, b, p0, p1, cb, j, cnt);
            out4[(size_t)(b * NP + p) * (DIM / 4) + cb + j] = v;
        }
    }
}

// ---------------- launch ----------------
static const size_t SMEM_MAIN =
    (size_t)(2 * NC * CHW + 2 * CAP * CHW) * sizeof(float4) + (2 * NP + CAP) * sizeof(int);

extern "C" void kernel_launch(void* const* d_in, const int* in_sizes, int n_in,
                              void* d_out, int out_size) {
    const void*  pairs = d_in[0];
    const float* score = (const float*)d_in[1];
    const float* lw    = (const float*)d_in[2];
    const float* lb    = (const float*)d_in[3];
    float* out = (float*)d_out;
    (void)in_sizes; (void)n_in; (void)out_size;

    cudaFuncSetAttribute(k_main, cudaFuncAttributeMaxDynamicSharedMemorySize, (int)SMEM_MAIN);

    k_prep  <<<NB + 1, 256>>>(pairs, score);
    k_trans <<<dim3(19, 64), dim3(32, 8)>>>(lw);
    k_tables<<<dim3(19, 2, 8), 64>>>(lb);
    k_main  <<<296, TPB, SMEM_MAIN>>>(pairs, out);
}

// round 5
// speedup vs baseline: 2.0444x; 1.3299x over previous
#include <cuda_runtime.h>
#include <stdint.h>

#define NC   151          // classes incl. background
#define CM1  150
#define DIM  2048
#define NB   128          // images
#define NP   512          // pairs per image
#define CAP  16           // max absent classes handled in smem (fallback beyond)
#define CHW  16           // float4 per chunk row (64 floats)
#define NCHUNK (DIM / 4 / CHW)   // 32
#define TPB  1024

// ---------------- device scratch ----------------
__device__ float g_sym[NC * NC];
__device__ float g_WT[600 * DIM];         // lin_w transposed
__device__ float g_T0[NC * DIM];
__device__ float g_T1[NC * DIM];
__device__ int   g_abs_cnt[NB];
__device__ int   g_abs_list[NB * CM1];

// ---------------- float4 helpers ----------------
__device__ __forceinline__ float4 f4add(float4 a, float4 b) {
    return make_float4(a.x + b.x, a.y + b.y, a.z + b.z, a.w + b.w);
}
__device__ __forceinline__ float4 f4fma(float s, float4 a, float4 acc) {
    acc.x = fmaf(s, a.x, acc.x); acc.y = fmaf(s, a.y, acc.y);
    acc.z = fmaf(s, a.z, acc.z); acc.w = fmaf(s, a.w, acc.w);
    return acc;
}
__device__ __forceinline__ float4 f4fms(float s, float4 a, float4 acc) {
    acc.x = fmaf(-s, a.x, acc.x); acc.y = fmaf(-s, a.y, acc.y);
    acc.z = fmaf(-s, a.z, acc.z); acc.w = fmaf(-s, a.w, acc.w);
    return acc;
}

// int64-vs-int32 detection (all pair values >= 1, little-endian)
__device__ __forceinline__ int pairs_is64(const int* p32) { return (p32[1] == 0) ? 1 : 0; }

// ---------------- kernel 1: fused sym + absent lists + weight transpose ----------------
// blocks [0]           : sym table
// blocks [1, NB]       : per-image absent lists
// blocks [NB+1, ...)   : 32x32 transpose tiles of lin_w
__global__ void k_setup(const void* __restrict__ pairs_v,
                        const float* __restrict__ score,
                        const float* __restrict__ w) {
    const int* p32 = (const int*)pairs_v;
    int tid = threadIdx.x;
    if (blockIdx.x == 0) {
        for (int idx = tid; idx < NC * NC; idx += blockDim.x) {
            int c = idx / NC, e = idx % NC;
            g_sym[idx] = 0.5f * (score[c * NC + e] + score[e * NC + c]);
        }
    } else if (blockIdx.x <= NB) {
        int b = blockIdx.x - 1;
        int is64 = pairs_is64(p32);
        __shared__ int flags[NC];
        for (int i = tid; i < NC; i += blockDim.x) flags[i] = 0;
        __syncthreads();
        for (int i = tid; i < 2 * NP; i += blockDim.x) {
            size_t ei = (size_t)b * 2 * NP + i;
            flags[p32[ei << is64]] = 1;
        }
        __syncthreads();
        if (tid == 0) {
            int cnt = 0;
            for (int e = 1; e < NC; ++e)
                if (!flags[e]) g_abs_list[b * CM1 + cnt++] = e;
            g_abs_cnt[b] = cnt;
        }
    } else {
        // transpose tile: lin_w [2048,600] -> WT [600,2048]
        int t_id = blockIdx.x - (NB + 1);        // 0 .. 19*64-1
        int j0 = (t_id % 19) * 32, d0 = (t_id / 19) * 32;
        __shared__ float t[32][33];
        int tx = tid & 31, ty = tid >> 5;        // 256 threads -> (32, 8)
        for (int r = ty; r < 32; r += 8) {
            int d = d0 + r, j = j0 + tx;
            t[r][tx] = (j < 600) ? w[(size_t)d * 600 + j] : 0.f;
        }
        __syncthreads();
        for (int r = ty; r < 32; r += 8) {
            int j = j0 + r;
            if (j < 600) g_WT[(size_t)j * DIM + d0 + tx] = t[tx][r];
        }
    }
}

// ---------------- kernel 2: dense class tables T0/T1 ----------------
// grid (38, 2, 4), block 128. 4 classes x 128 float4-cols per block; e-loop
// unrolled x6 for memory-level parallelism (~6 LDGs in flight).
__global__ void k_tables(const float* __restrict__ lb) {
    int which = blockIdx.y;
    int cBase = blockIdx.x * 4;
    __shared__ float ssym[4][NC + 1];
    int tid = threadIdx.x;
    for (int idx = tid; idx < 4 * NC; idx += 128) {
        int ci = idx / NC, e = idx % NC;
        int c = cBase + ci;
        ssym[ci][e] = (c < NC) ? g_sym[c * NC + e] : 0.f;
    }
    __syncthreads();
    const float4* WT4 = (const float4*)g_WT;
    int d4 = blockIdx.z * 128 + tid;             // 0..511
    float4 acc[4];
#pragma unroll
    for (int ci = 0; ci < 4; ++ci) acc[ci] = make_float4(0.f, 0.f, 0.f, 0.f);
    int base = which * CM1;
#pragma unroll 6
    for (int e = 1; e < NC; ++e) {
        float4 wv = WT4[(size_t)(base + e - 1) * (DIM / 4) + d4];
#pragma unroll
        for (int ci = 0; ci < 4; ++ci) acc[ci] = f4fma(ssym[ci][e], wv, acc[ci]);
    }
    float4 hb = ((const float4*)lb)[d4];
    hb.x *= 0.5f; hb.y *= 0.5f; hb.z *= 0.5f; hb.w *= 0.5f;
    float* Tdst = which ? g_T1 : g_T0;
#pragma unroll
    for (int ci = 0; ci < 4; ++ci) {
        int c = cBase + ci;
        if (c >= NC) continue;
        float4 v = f4add(acc[ci], hb);
        if (c >= 1) {
            float4 pv = WT4[(size_t)(300 + which * CM1 + c - 1) * (DIM / 4) + d4];
            v = f4add(v, pv);
        }
        ((float4*)Tdst)[(size_t)c * (DIM / 4) + d4] = v;
    }
}

// ---------------- rare exact fallback (keeps main loop register-lean) ----------------
__device__ __noinline__ float4 fallback_corr(float4 v, int b, int p0, int p1,
                                             int cb, int j, int cnt) {
    const float4* WT4 = (const float4*)g_WT;
    for (int k = CAP; k < cnt; ++k) {
        int e = g_abs_list[b * CM1 + k];
        float4 a  = WT4[(size_t)(e - 1) * (DIM / 4) + cb + j];
        float4 bb = WT4[(size_t)(CM1 + e - 1) * (DIM / 4) + cb + j];
        v = f4fms(g_sym[p0 * NC + e], a, v);
        v = f4fms(g_sym[p1 * NC + e], bb, v);
    }
    return v;
}

// ---------------- kernel 3: persistent gather/add ----------------
// grid 296 (2 blocks/SM), 1024 threads, ~89.7KB dynamic smem each.
__global__ void __launch_bounds__(TPB, 2) k_main(const void* __restrict__ pairs_v,
                                                 float* __restrict__ out) {
    extern __shared__ float4 smem[];
    float4* s0 = smem;                       // NC*CHW
    float4* s1 = s0 + NC * CHW;              // NC*CHW
    float4* wa = s1 + NC * CHW;              // CAP*CHW
    float4* wb = wa + CAP * CHW;             // CAP*CHW
    int* sp = (int*)(wb + CAP * CHW);        // 2*NP = 1024
    int* slist = sp + 2 * NP;                // CAP
    __shared__ int scnt;

    const int* p32 = (const int*)pairs_v;
    int is64 = pairs_is64(p32);
    int tid = threadIdx.x;
    const float4* T04 = (const float4*)g_T0;
    const float4* T14 = (const float4*)g_T1;
    const float4* WT4 = (const float4*)g_WT;
    float4* out4 = (float4*)out;

    const int nitems = NCHUNK * NB;          // 4096
    int start = (int)(((long)nitems * blockIdx.x) / gridDim.x);
    int end   = (int)(((long)nitems * (blockIdx.x + 1)) / gridDim.x);
    int cur_chunk = -1;

    for (int item = start; item < end; ++item) {
        int chunk = item >> 7;               // item / NB
        int b = item & (NB - 1);
        int cb = chunk * CHW;

        __syncthreads();                     // protect smem reuse from prior item
        if (chunk != cur_chunk) {
            for (int idx = tid; idx < NC * CHW; idx += TPB) {
                int c = idx / CHW, j = idx % CHW;
                s0[idx] = T04[(size_t)c * (DIM / 4) + cb + j];
                s1[idx] = T14[(size_t)c * (DIM / 4) + cb + j];
            }
            cur_chunk = chunk;
        }
        sp[tid] = p32[((size_t)b * 2 * NP + tid) << is64];
        if (tid < CAP) slist[tid] = g_abs_list[b * CM1 + tid];
        if (tid == 0) scnt = g_abs_cnt[b];
        __syncthreads();

        int cnt = scnt;
        int kc = cnt < CAP ? cnt : CAP;
        for (int idx = tid; idx < kc * CHW; idx += TPB) {
            int k = idx / CHW, j = idx % CHW;
            int e = slist[k];
            wa[idx] = WT4[(size_t)(e - 1) * (DIM / 4) + cb + j];
            wb[idx] = WT4[(size_t)(CM1 + e - 1) * (DIM / 4) + cb + j];
        }
        if (kc) __syncthreads();

        int j = tid & (CHW - 1), sub = tid >> 4;   // sub in 0..63
#pragma unroll 4
        for (int it = 0; it < NP / 64; ++it) {
            int p = it * 64 + sub;
            int p0 = sp[2 * p], p1 = sp[2 * p + 1];
            float4 v = f4add(s0[p0 * CHW + j], s1[p1 * CHW + j]);
            for (int k = 0; k < kc; ++k) {
                int e = slist[k];
                v = f4fms(g_sym[p0 * NC + e], wa[k * CHW + j], v);
                v = f4fms(g_sym[p1 * NC + e], wb[k * CHW + j], v);
            }
            if (cnt > CAP) v = fallback_corr(v, b, p0, p1, cb, j, cnt);
            __stcs(&out4[(size_t)(b * NP + p) * (DIM / 4) + cb + j], v);
        }
    }
}

// ---------------- launch ----------------
static const size_t SMEM_MAIN =
    (size_t)(2 * NC * CHW + 2 * CAP * CHW) * sizeof(float4) + (2 * NP + CAP) * sizeof(int);

extern "C" void kernel_launch(void* const* d_in, const int* in_sizes, int n_in,
                              void* d_out, int out_size) {
    const void*  pairs = d_in[0];
    const float* score = (const float*)d_in[1];
    const float* lw    = (const float*)d_in[2];
    const float* lb    = (const float*)d_in[3];
    float* out = (float*)d_out;
    (void)in_sizes; (void)n_in; (void)out_size;

    cudaFuncSetAttribute(k_main, cudaFuncAttributeMaxDynamicSharedMemorySize, (int)SMEM_MAIN);

    k_setup <<<NB + 1 + 19 * 64, 256>>>(pairs, score, lw);
    k_tables<<<dim3(38, 2, 4), 128>>>(lb);
    k_main  <<<296, TPB, SMEM_MAIN>>>(pairs, out);
}